// round 13
// baseline (speedup 1.0000x reference)
#include <cuda_runtime.h>

namespace {

constexpr int NQ     = 12;
constexpr int DEPTH  = 6;
constexpr int NSTATE = 1 << NQ;        // 4096
constexpr int NT     = 256;            // threads per CTA
constexpr int PT     = NSTATE / NT;    // 16 amplitudes per thread

// Swizzle: S(x) = x ^ ((x>>4)&0xF) ^ 0xD*bit5(x).  GF(2)-linear.
// Chosen so that C/B/A patterns AND the Gray-inverse permuted store are all
// bank-conflict-free per half-warp (store matrix y ^ 0xD*y1 ^ 0xF*y0 invertible).
__device__ __forceinline__ int swz(int x) {
    return x ^ ((x >> 4) & 0xF) ^ (((x >> 5) & 1) * 0xD);
}
// 12-bit Gray-code inverse (prefix XOR)
__device__ __forceinline__ int ginv12(int v) {
    v ^= v >> 1; v ^= v >> 2; v ^= v >> 4; v ^= v >> 8;
    return v & 0xFFF;
}

__device__ __forceinline__ float2 cmul(float2 a, float2 b) {
    float2 r;
    r.x = fmaf(a.x, b.x, -(a.y * b.y));
    r.y = fmaf(a.x, b.y, a.y * b.x);
    return r;
}
__device__ __forceinline__ float2 cmulc(float2 a, float2 b) {  // a * conj(b)
    float2 r;
    r.x = fmaf(a.x, b.x,  a.y * b.y);
    r.y = fmaf(a.y, b.x, -(a.x * b.y));
    return r;
}
// shear pair (fast Givens): na = a - t*b ; nb = t*a + b   (4 FMA total)
__device__ __forceinline__ void sh_pair(float2& a, float2& b, float tv) {
    float2 na, nb;
    na.x = fmaf(-tv, b.x, a.x);
    na.y = fmaf(-tv, b.y, a.y);
    nb.x = fmaf( tv, a.x, b.x);
    nb.y = fmaf( tv, a.y, b.y);
    a = na; b = nb;
}

__global__ void __launch_bounds__(NT, 4) qsim_kernel(const float* __restrict__ x,
                                                     const float* __restrict__ params,
                                                     float* __restrict__ out)
{
    __shared__ float2 sS[NSTATE];          // state (32 KB), swizzled
    __shared__ float2 sU0[NQ][4];          // layer-0 full matrices (batch-dependent)
    __shared__ float  sT [DEPTH][NQ];      // shear coeff t = s'/c' (<=1), d>=1
    __shared__ float  sSc[DEPTH][NQ];      // per-gate scale c'
    __shared__ float2 sB1[DEPTH][NQ];      // B-diag b1 (b0 == 1 gauge), d>=1
    __shared__ float2 sA0[DEPTH][NQ];      // A-diag a0 (temp, for G0)
    __shared__ float2 sG [DEPTH][NQ];      // g = a1*conj(a0)
    __shared__ float2 sG0[DEPTH];          // prod_i a0[d][i], d=1..4
    __shared__ float  sCd[DEPTH];          // prod_i scale[d][i], d=1..5
    __shared__ int    sM [DEPTH];          // per-layer X-flip mask (wire i -> bit 11-i)
    __shared__ float2 sPhiA[DEPTH - 1][16];     // phase over t bits [7:4]
    __shared__ float2 sPhiB[DEPTH - 1][2][16];  // phase over t bits [3:0] (x bit4)
    __shared__ float2 sThi [DEPTH - 1][2][16];  // phase over r bits (x bit7 coupling)
    __shared__ float2 sW1[2][16];               // layer-1 fused product/diag table
    __shared__ float  sRed[NT / 32][NQ];

    const int t = threadIdx.x;
    const int b = blockIdx.x;

    if (t < DEPTH) sM[t] = 0;
    __syncthreads();

    // ================= Stage A: build gates; decompose U = (A*RY*B)*X =======
    if (t < DEPTH * NQ) {
        const int d = t / NQ, i = t % NQ;
        const float* pp = params + (d * NQ + i) * 3;
        float sa, ca, sb, cb, sg, cg;
        sincosf(0.5f * pp[0], &sa, &ca);
        sincosf(0.5f * pp[1], &sb, &cb);
        sincosf(0.5f * pp[2], &sg, &cg);
        float2 m00 = {  cb * ca, -sb * ca };
        float2 m01 = { -cb * sa,  sb * sa };
        float2 m10 = {  cb * sa,  sb * sa };
        float2 m11 = {  cb * ca,  sb * ca };
        float2 u00 = { cg * m00.x + sg * m10.y, cg * m00.y - sg * m10.x };
        float2 u01 = { cg * m01.x + sg * m11.y, cg * m01.y - sg * m11.x };
        float2 u10 = { sg * m00.y + cg * m10.x, -sg * m00.x + cg * m10.y };
        float2 u11 = { sg * m01.y + cg * m11.x, -sg * m01.x + cg * m11.y };
        if (d == 0) {
            float sx, cx;
            sincosf(0.5f * x[b * NQ + i], &sx, &cx);
            float2 v00 = { cx * u00.x + sx * u01.y,  cx * u00.y - sx * u01.x };
            float2 v01 = { sx * u00.y + cx * u01.x, -sx * u00.x + cx * u01.y };
            float2 v10 = { cx * u10.x + sx * u11.y,  cx * u10.y - sx * u11.x };
            float2 v11 = { sx * u10.y + cx * u11.x, -sx * u10.x + cx * u11.y };
            sU0[i][0] = v00; sU0[i][1] = v01; sU0[i][2] = v10; sU0[i][3] = v11;
        } else {
            float n00 = fmaf(u00.x, u00.x, u00.y * u00.y);
            float n10 = fmaf(u10.x, u10.x, u10.y * u10.y);
            bool swp = n10 > n00;     // V = U*X (column swap) so c' >= s'
            float2 v00, v10, v11;
            if (swp) { v00 = u01; v10 = u11; v11 = u10; atomicOr(&sM[d], 1 << (11 - i)); }
            else     { v00 = u00; v10 = u10; v11 = u11; }
            float c = sqrtf(fmaf(v00.x, v00.x, v00.y * v00.y));
            float s = sqrtf(fmaf(v10.x, v10.x, v10.y * v10.y));
            float ic = 1.0f / c;
            float2 a0 = { v00.x * ic, v00.y * ic };
            float2 a1, b1;
            if (s < 1e-12f) {
                a1 = { v11.x * ic, v11.y * ic };
                b1 = { 1.f, 0.f };
            } else {
                float is = 1.0f / s;
                a1 = { v10.x * is, v10.y * is };
                float2 tb = cmulc(v11, a1);
                b1 = { tb.x * ic, tb.y * ic };
            }
            sT [d][i] = s * ic;
            sSc[d][i] = c;
            sB1[d][i] = b1;
            sA0[d][i] = a0;
            sG [d][i] = cmulc(a1, a0);
        }
    }
    __syncthreads();

    // ================= Stage B: per-layer products =========================
    if (t >= 1 && t <= 5) {
        float cs = 1.f;
        #pragma unroll
        for (int i = 0; i < NQ; ++i) cs *= sSc[t][i];
        sCd[t] = cs;
        if (t <= 4) {
            float2 p = { 1.f, 0.f };
            #pragma unroll
            for (int i = 0; i < NQ; ++i) p = cmul(p, sA0[t][i]);
            sG0[t] = p;
        }
    }
    __syncthreads();

    // ================= Stage C: factorized diagonal tables =================
    // dst = (r<<8)|t ; logical src = gray(dst) ^ gm_d (performed by layer d-1's store).
    // D_d(dst) = PhiA[t>>4] * PhiB[bit4(t)][t&15] * Thi[bit7(t)][r].
    if (t < (DEPTH - 1) * 16) {            // PhiA: t bits 7..4 (wires 4..7)
        const int k = t >> 4, h = t & 15;
        const int d = k + 1;
        const int mm = sM[d];
        const int gm = mm ^ (mm >> 1);
        float2 P = (d >= 2) ? sG0[d - 1] : make_float2(1.f, 0.f);
        const float cd = sCd[d];
        P.x *= cd; P.y *= cd;
        #pragma unroll
        for (int i = 4; i <= 7; ++i)       // wire i -> t bit (11-i) = h bit (7-i)
            if ((h >> (7 - i)) & 1) P = cmul(P, sB1[d][i]);
        if (d >= 2) {                      // couplings i=5,6,7: t bits (6,7),(5,6),(4,5)
            if (((h >> 2) ^ (h >> 3) ^ (gm >> 6)) & 1) P = cmul(P, sG[d - 1][5]);
            if (((h >> 1) ^ (h >> 2) ^ (gm >> 5)) & 1) P = cmul(P, sG[d - 1][6]);
            if (((h >> 0) ^ (h >> 1) ^ (gm >> 4)) & 1) P = cmul(P, sG[d - 1][7]);
        }
        sPhiA[k][h] = P;
    } else if (t < (DEPTH - 1) * 16 + (DEPTH - 1) * 32) {  // PhiB: t bits 3..0 (x bit4)
        const int tt = t - (DEPTH - 1) * 16;
        const int k = tt >> 5, e4 = (tt >> 4) & 1, l = tt & 15;
        const int d = k + 1;
        const int mm = sM[d];
        const int gm = mm ^ (mm >> 1);
        float2 P = { 1.f, 0.f };
        #pragma unroll
        for (int i = 8; i <= 11; ++i)      // wire i -> t bit (11-i) = l bit (11-i)
            if ((l >> (11 - i)) & 1) P = cmul(P, sB1[d][i]);
        if (d >= 2) {
            if (((l >> 3) ^ e4       ^ (gm >> 3)) & 1) P = cmul(P, sG[d - 1][8]);   // bits 3^4
            if (((l >> 2) ^ (l >> 3) ^ (gm >> 2)) & 1) P = cmul(P, sG[d - 1][9]);   // bits 2^3
            if (((l >> 1) ^ (l >> 2) ^ (gm >> 1)) & 1) P = cmul(P, sG[d - 1][10]);  // bits 1^2
            if (((l >> 0) ^ (l >> 1) ^ (gm >> 0)) & 1) P = cmul(P, sG[d - 1][11]);  // bits 0^1
        }
        sPhiB[k][e4][l] = P;
    }
    if (t < (DEPTH - 1) * 32) {            // Thi: wires 0..3 (+ couplings 0..4)
        const int k = t / 32, e = (t >> 4) & 1, r = t & 15;
        const int d = k + 1;
        const int mm = sM[d];
        const int gm = mm ^ (mm >> 1);
        float2 T = { 1.f, 0.f };
        #pragma unroll
        for (int i = 0; i < 4; ++i)
            if ((r >> (3 - i)) & 1) T = cmul(T, sB1[d][i]);
        if (d >= 2) {
            int r0 = r & 1, r1 = (r >> 1) & 1, r2 = (r >> 2) & 1, r3 = (r >> 3) & 1;
            if ((r3      ^ (gm >> 11)) & 1) T = cmul(T, sG[d - 1][0]);
            if ((r2 ^ r3 ^ (gm >> 10)) & 1) T = cmul(T, sG[d - 1][1]);
            if ((r1 ^ r2 ^ (gm >>  9)) & 1) T = cmul(T, sG[d - 1][2]);
            if ((r0 ^ r1 ^ (gm >>  8)) & 1) T = cmul(T, sG[d - 1][3]);
            if ((e  ^ r0 ^ (gm >>  7)) & 1) T = cmul(T, sG[d - 1][4]);
        }
        sThi[k][e][r] = T;
    }
    __syncthreads();

    // ================= Stage D: layer-1 fused table + per-thread phiF ======
    const int m1g = sM[1] ^ (sM[1] >> 1);
    if (t < 32) {
        const int e = t >> 4, r = t & 15;
        const int gr = (r ^ (r >> 1)) ^ ((m1g >> 8) & 15);
        float2 c01 = cmul(sU0[0][(gr & 8) ? 2 : 0], sU0[1][(gr & 4) ? 2 : 0]);
        float2 c23 = cmul(sU0[2][(gr & 2) ? 2 : 0], sU0[3][(gr & 1) ? 2 : 0]);
        float2 u4  = sU0[4][((e ^ r ^ (m1g >> 7)) & 1) ? 2 : 0];
        sW1[e][r] = cmul(cmul(c01, c23), cmul(u4, sThi[0][0][r]));
    }
    const int gt = t ^ (t >> 1);
    float2 phiF;
    {
        float2 p = cmul(sPhiA[0][t >> 4], sPhiB[0][(t >> 4) & 1][t & 15]);
        const int gmix = gt ^ m1g;
        #pragma unroll
        for (int i = 5; i < NQ; ++i) {
            int bit = (gmix >> (11 - i)) & 1;
            p = cmul(p, sU0[i][bit ? 2 : 0]);
        }
        phiF = p;
    }
    __syncthreads();

    // ===== addressing bases (swizzle S; all GF(2)-linear) ==================
    const int swt     = swz(t);                      // C: (r<<8) | swt  (immediate offs)
    const int baseB   = ((t >> 4) << 8) | (t & 15);  // B: bits7..4 zero -> S = identity
    const int swA     = swz(t << 4);                 // A load: swA ^ r
    const int swGinvT = swz(ginv12(t << 4));         // A store base (pre-mask)

    float2 s[PT];

    // ================= Layers 1..5 =========================================
    for (int d = 1; d < DEPTH; ++d) {
        // ---- Round C: wires 0..3 (read set == write set: no internal sync)
        if (d == 1) {
            const float2* w1 = sW1[t >> 7];
            #pragma unroll
            for (int r = 0; r < PT; ++r) s[r] = cmul(w1[r], phiF);
        } else {
            const int k = d - 1;
            const float2 phi = cmul(sPhiA[k][t >> 4], sPhiB[k][(t >> 4) & 1][t & 15]);
            const float2* thi = sThi[k][(t >> 7) & 1];
            #pragma unroll
            for (int r = 0; r < PT; ++r)
                s[r] = cmul(sS[(r << 8) | swt], cmul(phi, thi[r]));
        }
        #pragma unroll
        for (int j = 0; j < 4; ++j) {  // wire j -> local bit 3-j
            const int p = 3 - j;
            const float tv = sT[d][j];
            #pragma unroll
            for (int m = 0; m < 8; ++m) {
                int lo = m & ((1 << p) - 1);
                int i0 = ((m >> p) << (p + 1)) | lo;
                sh_pair(s[i0], s[i0 | (1 << p)], tv);
            }
        }
        #pragma unroll
        for (int r = 0; r < PT; ++r) sS[(r << 8) | swt] = s[r];
        __syncthreads();

        // ---- Round B: wires 4..7 ----
        #pragma unroll
        for (int r = 0; r < PT; ++r) {
            const int off = (r << 4) ^ r ^ (((r >> 1) & 1) * 0xD);  // S(r<<4)
            s[r] = sS[baseB ^ off];
        }
        #pragma unroll
        for (int j = 0; j < 4; ++j) {
            const int p = 3 - j;
            const float tv = sT[d][4 + j];
            #pragma unroll
            for (int m = 0; m < 8; ++m) {
                int lo = m & ((1 << p) - 1);
                int i0 = ((m >> p) << (p + 1)) | lo;
                sh_pair(s[i0], s[i0 | (1 << p)], tv);
            }
        }
        #pragma unroll
        for (int r = 0; r < PT; ++r) {
            const int off = (r << 4) ^ r ^ (((r >> 1) & 1) * 0xD);
            sS[baseB ^ off] = s[r];
        }
        __syncthreads();

        // ---- Round A: wires 8..11; store PERMUTED for the next layer ----
        #pragma unroll
        for (int r = 0; r < PT; ++r) s[r] = sS[swA ^ r];
        #pragma unroll
        for (int j = 0; j < 4; ++j) {
            const int p = 3 - j;
            const float tv = sT[d][8 + j];
            #pragma unroll
            for (int m = 0; m < 8; ++m) {
                int lo = m & ((1 << p) - 1);
                int i0 = ((m >> p) << (p + 1)) | lo;
                sh_pair(s[i0], s[i0 | (1 << p)], tv);
            }
        }
        if (d < DEPTH - 1) {
            // stored[dst] = value(idx), dst = ginv(idx ^ gm_{d+1}).
            // ALL threads must finish their round-A loads before ANY permuted
            // store (write set belongs to other threads' read sets).
            __syncthreads();
            const int mmN = sM[d + 1];
            const int gvN = ginv12(mmN ^ (mmN >> 1));
            const int sbase = swGinvT ^ swz(gvN);
            #pragma unroll
            for (int r = 0; r < PT; ++r) {
                const int gr4 = r ^ (r >> 1) ^ (r >> 2) ^ (r >> 3);  // ginv(r)
                sS[sbase ^ gr4] = s[r];
            }
            __syncthreads();
        }
    }

    // ==== Final reduction directly from registers (idx = (t<<4)|r). ====
    float accLo[4] = { 0.f, 0.f, 0.f, 0.f };
    float sumAll = 0.f;
    #pragma unroll
    for (int r = 0; r < PT; ++r) {
        float pr = fmaf(s[r].x, s[r].x, s[r].y * s[r].y);
        sumAll += pr;
        const int r3 = (r >> 3) & 1, r2 = (r >> 2) & 1, r1 = (r >> 1) & 1, r0 = r & 1;
        const int p8 = r3, p9 = r3 ^ r2, p10 = p9 ^ r1, p11 = p10 ^ r0;
        accLo[0] += p8  ? -pr : pr;
        accLo[1] += p9  ? -pr : pr;
        accLo[2] += p10 ? -pr : pr;
        accLo[3] += p11 ? -pr : pr;
    }

    float acc[NQ];
    int pref = 0;
    #pragma unroll
    for (int q = 0; q < 8; ++q) {
        pref ^= (t >> (7 - q)) & 1;
        acc[q] = pref ? -sumAll : sumAll;
    }
    const int ptp = pref;
    #pragma unroll
    for (int q = 0; q < 4; ++q) acc[8 + q] = ptp ? -accLo[q] : accLo[q];

    #pragma unroll
    for (int q = 0; q < NQ; ++q) {
        #pragma unroll
        for (int off = 16; off; off >>= 1)
            acc[q] += __shfl_xor_sync(0xffffffffu, acc[q], off);
    }
    if ((t & 31) == 0) {
        #pragma unroll
        for (int q = 0; q < NQ; ++q) sRed[t >> 5][q] = acc[q];
    }
    __syncthreads();
    if (t < NQ) {
        float sres = 0.f;
        #pragma unroll
        for (int w = 0; w < NT / 32; ++w) sres += sRed[w][t];
        out[b * NQ + t] = sres;
    }
}

} // namespace

extern "C" void kernel_launch(void* const* d_in, const int* in_sizes, int n_in,
                              void* d_out, int out_size)
{
    (void)n_in; (void)out_size;
    const float* x;
    const float* params;
    if (in_sizes[0] == DEPTH * NQ * 3) {
        params = (const float*)d_in[0];
        x      = (const float*)d_in[1];
    } else {
        x      = (const float*)d_in[0];
        params = (const float*)d_in[1];
    }
    qsim_kernel<<<4096, NT>>>(x, params, (float*)d_out);
}

// round 14
// speedup vs baseline: 1.0509x; 1.0509x over previous
#include <cuda_runtime.h>

namespace {

constexpr int NQ     = 12;
constexpr int DEPTH  = 6;
constexpr int NSTATE = 1 << NQ;        // 4096
constexpr int NT     = 256;            // threads per CTA
constexpr int PT     = NSTATE / NT;    // 16 amplitudes per thread
constexpr int NPAD   = NSTATE + (NSTATE >> 4);   // 4352: pad-17 rows

// Padded linear layout: phys(idx) = idx + (idx>>4) = 17*(idx>>4) + (idx&15).

__device__ __forceinline__ float2 cmul(float2 a, float2 b) {
    float2 r;
    r.x = fmaf(a.x, b.x, -(a.y * b.y));
    r.y = fmaf(a.x, b.y, a.y * b.x);
    return r;
}
__device__ __forceinline__ float2 cmulc(float2 a, float2 b) {  // a * conj(b)
    float2 r;
    r.x = fmaf(a.x, b.x,  a.y * b.y);
    r.y = fmaf(a.y, b.x, -(a.x * b.y));
    return r;
}
// shear pair (fast Givens): na = a - t*b ; nb = t*a + b   (4 FMA total)
__device__ __forceinline__ void sh_pair(float2& a, float2& b, float tv) {
    float2 na, nb;
    na.x = fmaf(-tv, b.x, a.x);
    na.y = fmaf(-tv, b.y, a.y);
    nb.x = fmaf( tv, a.x, b.x);
    nb.y = fmaf( tv, a.y, b.y);
    a = na; b = nb;
}
// 4 wires over local bits 3..0 (tv0 acts on bit 3, ..., tv3 on bit 0)
__device__ __forceinline__ void gate4(float2* s, float tv0, float tv1, float tv2, float tv3) {
    #pragma unroll
    for (int m = 0; m < 8; ++m) sh_pair(s[m], s[m + 8], tv0);
    #pragma unroll
    for (int m = 0; m < 8; ++m) {
        int i0 = ((m >> 2) << 3) | (m & 3);
        sh_pair(s[i0], s[i0 | 4], tv1);
    }
    #pragma unroll
    for (int m = 0; m < 8; ++m) {
        int i0 = ((m >> 1) << 2) | (m & 1);
        sh_pair(s[i0], s[i0 | 2], tv2);
    }
    #pragma unroll
    for (int m = 0; m < 8; ++m) {
        int i0 = m << 1;
        sh_pair(s[i0], s[i0 | 1], tv3);
    }
}

__global__ void __launch_bounds__(NT, 4) qsim_kernel(const float* __restrict__ x,
                                                     const float* __restrict__ params,
                                                     float* __restrict__ out)
{
    __shared__ float2 sS[NPAD];            // state, padded layout (34.0 KB)
    __shared__ float2 sU0[NQ][4];          // layer-0 full matrices (batch-dependent)
    __shared__ float  sT [DEPTH][NQ];      // shear coeff t = s'/c' (<=1), d>=1
    __shared__ float  sSc[DEPTH][NQ];      // per-gate scale c'
    __shared__ float2 sB1[DEPTH][NQ];      // B-diag b1 (b0 == 1 gauge), d>=1
    __shared__ float2 sA0[DEPTH][NQ];      // A-diag a0 (temp, for G0)
    __shared__ float2 sG [DEPTH][NQ];      // g = a1*conj(a0)
    __shared__ float2 sG0[DEPTH];          // prod_i a0[d][i], d=1..4
    __shared__ float  sCd[DEPTH];          // prod_i scale[d][i], d=1..5
    __shared__ int    sM [DEPTH];          // per-layer X-flip mask (wire i -> bit 11-i)
    __shared__ float2 sPhiA[DEPTH - 1][16];     // phase over t bits [7:4]
    __shared__ float2 sPhiB[DEPTH - 1][2][16];  // phase over t bits [3:0] (x bit4)
    __shared__ float2 sThi [DEPTH - 1][2][16];  // phase over r bits (x bit7 coupling)
    __shared__ float2 sW1[2][16];               // layer-1 fused product/diag table
    __shared__ float  sRed[NT / 32][NQ];

    const int t = threadIdx.x;
    const int b = blockIdx.x;

    if (t < DEPTH) sM[t] = 0;
    __syncthreads();

    // ================= Stage A: build gates; decompose U = (A*RY*B)*X =======
    if (t < DEPTH * NQ) {
        const int d = t / NQ, i = t % NQ;
        const float* pp = params + (d * NQ + i) * 3;
        float sa, ca, sb, cb, sg, cg;
        sincosf(0.5f * pp[0], &sa, &ca);
        sincosf(0.5f * pp[1], &sb, &cb);
        sincosf(0.5f * pp[2], &sg, &cg);
        float2 m00 = {  cb * ca, -sb * ca };
        float2 m01 = { -cb * sa,  sb * sa };
        float2 m10 = {  cb * sa,  sb * sa };
        float2 m11 = {  cb * ca,  sb * ca };
        float2 u00 = { cg * m00.x + sg * m10.y, cg * m00.y - sg * m10.x };
        float2 u01 = { cg * m01.x + sg * m11.y, cg * m01.y - sg * m11.x };
        float2 u10 = { sg * m00.y + cg * m10.x, -sg * m00.x + cg * m10.y };
        float2 u11 = { sg * m01.y + cg * m11.x, -sg * m01.x + cg * m11.y };
        if (d == 0) {
            float sx, cx;
            sincosf(0.5f * x[b * NQ + i], &sx, &cx);
            float2 v00 = { cx * u00.x + sx * u01.y,  cx * u00.y - sx * u01.x };
            float2 v01 = { sx * u00.y + cx * u01.x, -sx * u00.x + cx * u01.y };
            float2 v10 = { cx * u10.x + sx * u11.y,  cx * u10.y - sx * u11.x };
            float2 v11 = { sx * u10.y + cx * u11.x, -sx * u10.x + cx * u11.y };
            sU0[i][0] = v00; sU0[i][1] = v01; sU0[i][2] = v10; sU0[i][3] = v11;
        } else {
            float n00 = fmaf(u00.x, u00.x, u00.y * u00.y);
            float n10 = fmaf(u10.x, u10.x, u10.y * u10.y);
            bool swp = n10 > n00;     // V = U*X (column swap) so c' >= s'
            float2 v00, v10, v11;
            if (swp) { v00 = u01; v10 = u11; v11 = u10; atomicOr(&sM[d], 1 << (11 - i)); }
            else     { v00 = u00; v10 = u10; v11 = u11; }
            float c = sqrtf(fmaf(v00.x, v00.x, v00.y * v00.y));
            float s = sqrtf(fmaf(v10.x, v10.x, v10.y * v10.y));
            float ic = 1.0f / c;
            float2 a0 = { v00.x * ic, v00.y * ic };
            float2 a1, b1;
            if (s < 1e-12f) {
                a1 = { v11.x * ic, v11.y * ic };
                b1 = { 1.f, 0.f };
            } else {
                float is = 1.0f / s;
                a1 = { v10.x * is, v10.y * is };
                float2 tb = cmulc(v11, a1);
                b1 = { tb.x * ic, tb.y * ic };
            }
            sT [d][i] = s * ic;
            sSc[d][i] = c;
            sB1[d][i] = b1;
            sA0[d][i] = a0;
            sG [d][i] = cmulc(a1, a0);
        }
    }
    __syncthreads();

    // ================= Stage B: per-layer products =========================
    if (t >= 1 && t <= 5) {
        float cs = 1.f;
        #pragma unroll
        for (int i = 0; i < NQ; ++i) cs *= sSc[t][i];
        sCd[t] = cs;
        if (t <= 4) {
            float2 p = { 1.f, 0.f };
            #pragma unroll
            for (int i = 0; i < NQ; ++i) p = cmul(p, sA0[t][i]);
            sG0[t] = p;
        }
    }
    __syncthreads();

    // ================= Stage C: factorized diagonal tables =================
    // dst = (r<<8)|t ; src = gray(dst) ^ gm_d.
    // D_d(dst) = PhiA[t>>4] * PhiB[bit4(t)][t&15] * Thi[bit7(t)][r].
    if (t < (DEPTH - 1) * 16) {            // PhiA: t bits 7..4 (wires 4..7)
        const int k = t >> 4, h = t & 15;
        const int d = k + 1;
        const int mm = sM[d];
        const int gm = mm ^ (mm >> 1);
        float2 P = (d >= 2) ? sG0[d - 1] : make_float2(1.f, 0.f);
        const float cd = sCd[d];
        P.x *= cd; P.y *= cd;
        #pragma unroll
        for (int i = 4; i <= 7; ++i)       // wire i -> t bit (11-i) = h bit (7-i)
            if ((h >> (7 - i)) & 1) P = cmul(P, sB1[d][i]);
        if (d >= 2) {                      // couplings i=5,6,7: t bits (6,7),(5,6),(4,5)
            if (((h >> 2) ^ (h >> 3) ^ (gm >> 6)) & 1) P = cmul(P, sG[d - 1][5]);
            if (((h >> 1) ^ (h >> 2) ^ (gm >> 5)) & 1) P = cmul(P, sG[d - 1][6]);
            if (((h >> 0) ^ (h >> 1) ^ (gm >> 4)) & 1) P = cmul(P, sG[d - 1][7]);
        }
        sPhiA[k][h] = P;
    } else if (t < (DEPTH - 1) * 16 + (DEPTH - 1) * 32) {  // PhiB: t bits 3..0 (x bit4)
        const int tt = t - (DEPTH - 1) * 16;
        const int k = tt >> 5, e4 = (tt >> 4) & 1, l = tt & 15;
        const int d = k + 1;
        const int mm = sM[d];
        const int gm = mm ^ (mm >> 1);
        float2 P = { 1.f, 0.f };
        #pragma unroll
        for (int i = 8; i <= 11; ++i)      // wire i -> t bit (11-i) = l bit (11-i)
            if ((l >> (11 - i)) & 1) P = cmul(P, sB1[d][i]);
        if (d >= 2) {
            if (((l >> 3) ^ e4       ^ (gm >> 3)) & 1) P = cmul(P, sG[d - 1][8]);   // bits 3^4
            if (((l >> 2) ^ (l >> 3) ^ (gm >> 2)) & 1) P = cmul(P, sG[d - 1][9]);   // bits 2^3
            if (((l >> 1) ^ (l >> 2) ^ (gm >> 1)) & 1) P = cmul(P, sG[d - 1][10]);  // bits 1^2
            if (((l >> 0) ^ (l >> 1) ^ (gm >> 0)) & 1) P = cmul(P, sG[d - 1][11]);  // bits 0^1
        }
        sPhiB[k][e4][l] = P;
    }
    if (t < (DEPTH - 1) * 32) {            // Thi: wires 0..3 (+ couplings 0..4)
        const int k = t / 32, e = (t >> 4) & 1, r = t & 15;
        const int d = k + 1;
        const int mm = sM[d];
        const int gm = mm ^ (mm >> 1);
        float2 T = { 1.f, 0.f };
        #pragma unroll
        for (int i = 0; i < 4; ++i)
            if ((r >> (3 - i)) & 1) T = cmul(T, sB1[d][i]);
        if (d >= 2) {
            int r0 = r & 1, r1 = (r >> 1) & 1, r2 = (r >> 2) & 1, r3 = (r >> 3) & 1;
            if ((r3      ^ (gm >> 11)) & 1) T = cmul(T, sG[d - 1][0]);
            if ((r2 ^ r3 ^ (gm >> 10)) & 1) T = cmul(T, sG[d - 1][1]);
            if ((r1 ^ r2 ^ (gm >>  9)) & 1) T = cmul(T, sG[d - 1][2]);
            if ((r0 ^ r1 ^ (gm >>  8)) & 1) T = cmul(T, sG[d - 1][3]);
            if ((e  ^ r0 ^ (gm >>  7)) & 1) T = cmul(T, sG[d - 1][4]);
        }
        sThi[k][e][r] = T;
    }
    __syncthreads();

    // ================= Stage D: layer-1 fused table + per-thread phiF ======
    const int m1g = sM[1] ^ (sM[1] >> 1);
    if (t < 32) {
        const int e = t >> 4, r = t & 15;
        const int gr = (r ^ (r >> 1)) ^ ((m1g >> 8) & 15);
        float2 c01 = cmul(sU0[0][(gr & 8) ? 2 : 0], sU0[1][(gr & 4) ? 2 : 0]);
        float2 c23 = cmul(sU0[2][(gr & 2) ? 2 : 0], sU0[3][(gr & 1) ? 2 : 0]);
        float2 u4  = sU0[4][((e ^ r ^ (m1g >> 7)) & 1) ? 2 : 0];
        sW1[e][r] = cmul(cmul(c01, c23), cmul(u4, sThi[0][0][r]));
    }
    const int gt = t ^ (t >> 1);
    float2 phiF;
    {
        float2 p = cmul(sPhiA[0][t >> 4], sPhiB[0][(t >> 4) & 1][t & 15]);
        const int gmix = gt ^ m1g;
        #pragma unroll
        for (int i = 5; i < NQ; ++i) {
            int bit = (gmix >> (11 - i)) & 1;
            p = cmul(p, sU0[i][bit ? 2 : 0]);
        }
        phiF = p;
    }
    __syncthreads();

    // ===== addressing bases (pad-17: phys = idx + (idx>>4)) ================
    const int swt_p   = t + (t >> 4);                              // C store: + 272r
    const int baseB_p = (((t >> 4) << 8) | (t & 15)) + ((t >> 4) << 4);  // B: + 17v
    const int baseA_p = 17 * t;                                    // A: + r

    float2 s[PT];

    // ================= Layer 1 (peeled): no gather, tables only ============
    {
        const float2* w1 = sW1[t >> 7];
        #pragma unroll
        for (int r = 0; r < PT; ++r) s[r] = cmul(w1[r], phiF);
        gate4(s, sT[1][0], sT[1][1], sT[1][2], sT[1][3]);
        #pragma unroll
        for (int r = 0; r < PT; ++r) sS[swt_p + 272 * r] = s[r];
        __syncthreads();

        #pragma unroll
        for (int r = 0; r < PT; ++r) s[r] = sS[baseB_p + 17 * r];
        gate4(s, sT[1][4], sT[1][5], sT[1][6], sT[1][7]);
        #pragma unroll
        for (int r = 0; r < PT; ++r) sS[baseB_p + 17 * r] = s[r];
        __syncthreads();

        #pragma unroll
        for (int r = 0; r < PT; ++r) s[r] = sS[baseA_p + r];
        gate4(s, sT[1][8], sT[1][9], sT[1][10], sT[1][11]);
        #pragma unroll
        for (int r = 0; r < PT; ++r) sS[baseA_p + r] = s[r];
        __syncthreads();
    }

    // ================= Layers 2..5 (fully unrolled) ========================
    #pragma unroll
    for (int d = 2; d < DEPTH; ++d) {
        const int k = d - 1;

        // ---- Round C: Gray gather + diagonal fused into load, wires 0..3 --
        {
            const int mm = sM[d];
            const int gIdx = gt ^ (mm ^ (mm >> 1));
            const float2 phi = cmul(sPhiA[k][t >> 4], sPhiB[k][(t >> 4) & 1][t & 15]);
            const float2* thi = sThi[k][(t >> 7) & 1];
            #pragma unroll
            for (int r = 0; r < PT; ++r) {
                const int gr = r ^ (r >> 1);
                const int cr = (gr << 8) ^ ((r & 1) << 7);   // logical src bits
                const int idxl = gIdx ^ cr;
                s[r] = cmul(sS[idxl + (idxl >> 4)], cmul(phi, thi[r]));
            }
            __syncthreads();           // all reads of old state done
        }
        gate4(s, sT[d][0], sT[d][1], sT[d][2], sT[d][3]);
        #pragma unroll
        for (int r = 0; r < PT; ++r) sS[swt_p + 272 * r] = s[r];
        __syncthreads();

        // ---- Round B: wires 4..7 (per-thread disjoint addresses) ----
        #pragma unroll
        for (int r = 0; r < PT; ++r) s[r] = sS[baseB_p + 17 * r];
        gate4(s, sT[d][4], sT[d][5], sT[d][6], sT[d][7]);
        #pragma unroll
        for (int r = 0; r < PT; ++r) sS[baseB_p + 17 * r] = s[r];
        __syncthreads();

        // ---- Round A: wires 8..11 ----
        #pragma unroll
        for (int r = 0; r < PT; ++r) s[r] = sS[baseA_p + r];
        gate4(s, sT[d][8], sT[d][9], sT[d][10], sT[d][11]);
        if (d < DEPTH - 1) {
            #pragma unroll
            for (int r = 0; r < PT; ++r) sS[baseA_p + r] = s[r];
            __syncthreads();
        }
    }

    // ==== Final reduction directly from registers (idx = (t<<4)|r). ====
    float accLo[4] = { 0.f, 0.f, 0.f, 0.f };
    float sumAll = 0.f;
    #pragma unroll
    for (int r = 0; r < PT; ++r) {
        float pr = fmaf(s[r].x, s[r].x, s[r].y * s[r].y);
        sumAll += pr;
        const int r3 = (r >> 3) & 1, r2 = (r >> 2) & 1, r1 = (r >> 1) & 1, r0 = r & 1;
        const int p8 = r3, p9 = r3 ^ r2, p10 = p9 ^ r1, p11 = p10 ^ r0;
        accLo[0] += p8  ? -pr : pr;
        accLo[1] += p9  ? -pr : pr;
        accLo[2] += p10 ? -pr : pr;
        accLo[3] += p11 ? -pr : pr;
    }

    float acc[NQ];
    int pref = 0;
    #pragma unroll
    for (int q = 0; q < 8; ++q) {
        pref ^= (t >> (7 - q)) & 1;
        acc[q] = pref ? -sumAll : sumAll;
    }
    const int ptp = pref;
    #pragma unroll
    for (int q = 0; q < 4; ++q) acc[8 + q] = ptp ? -accLo[q] : accLo[q];

    #pragma unroll
    for (int q = 0; q < NQ; ++q) {
        #pragma unroll
        for (int off = 16; off; off >>= 1)
            acc[q] += __shfl_xor_sync(0xffffffffu, acc[q], off);
    }
    if ((t & 31) == 0) {
        #pragma unroll
        for (int q = 0; q < NQ; ++q) sRed[t >> 5][q] = acc[q];
    }
    __syncthreads();
    if (t < NQ) {
        float sres = 0.f;
        #pragma unroll
        for (int w = 0; w < NT / 32; ++w) sres += sRed[w][t];
        out[b * NQ + t] = sres;
    }
}

} // namespace

extern "C" void kernel_launch(void* const* d_in, const int* in_sizes, int n_in,
                              void* d_out, int out_size)
{
    (void)n_in; (void)out_size;
    const float* x;
    const float* params;
    if (in_sizes[0] == DEPTH * NQ * 3) {
        params = (const float*)d_in[0];
        x      = (const float*)d_in[1];
    } else {
        x      = (const float*)d_in[0];
        params = (const float*)d_in[1];
    }
    qsim_kernel<<<4096, NT>>>(x, params, (float*)d_out);
}

// round 15
// speedup vs baseline: 1.0609x; 1.0095x over previous
#include <cuda_runtime.h>

namespace {

constexpr int NQ     = 12;
constexpr int DEPTH  = 6;
constexpr int NSTATE = 1 << NQ;        // 4096
constexpr int NT     = 256;            // threads per CTA
constexpr int PT     = NSTATE / NT;    // 16 amplitudes per thread
constexpr int NPAD   = NSTATE + (NSTATE >> 4);   // 4352: pad-17 rows

// Padded linear layout: phys(idx) = idx + (idx>>4) = 17*(idx>>4) + (idx&15).

__device__ __forceinline__ float2 cmul(float2 a, float2 b) {
    float2 r;
    r.x = fmaf(a.x, b.x, -(a.y * b.y));
    r.y = fmaf(a.x, b.y, a.y * b.x);
    return r;
}
__device__ __forceinline__ float2 cmulc(float2 a, float2 b) {  // a * conj(b)
    float2 r;
    r.x = fmaf(a.x, b.x,  a.y * b.y);
    r.y = fmaf(a.y, b.x, -(a.x * b.y));
    return r;
}
// shear pair (fast Givens): na = a - t*b ; nb = t*a + b   (4 FMA total)
__device__ __forceinline__ void sh_pair(float2& a, float2& b, float tv) {
    float2 na, nb;
    na.x = fmaf(-tv, b.x, a.x);
    na.y = fmaf(-tv, b.y, a.y);
    nb.x = fmaf( tv, a.x, b.x);
    nb.y = fmaf( tv, a.y, b.y);
    a = na; b = nb;
}
// 4 wires over local bits 3..0 (tv0 acts on bit 3, ..., tv3 on bit 0)
__device__ __forceinline__ void gate4(float2* s, float tv0, float tv1, float tv2, float tv3) {
    #pragma unroll
    for (int m = 0; m < 8; ++m) sh_pair(s[m], s[m + 8], tv0);
    #pragma unroll
    for (int m = 0; m < 8; ++m) {
        int i0 = ((m >> 2) << 3) | (m & 3);
        sh_pair(s[i0], s[i0 | 4], tv1);
    }
    #pragma unroll
    for (int m = 0; m < 8; ++m) {
        int i0 = ((m >> 1) << 2) | (m & 1);
        sh_pair(s[i0], s[i0 | 2], tv2);
    }
    #pragma unroll
    for (int m = 0; m < 8; ++m) {
        int i0 = m << 1;
        sh_pair(s[i0], s[i0 | 1], tv3);
    }
}

__global__ void __launch_bounds__(NT, 4) qsim_kernel(const float* __restrict__ x,
                                                     const float* __restrict__ params,
                                                     float* __restrict__ out)
{
    __shared__ float2 sS[NPAD];            // state, padded layout (34.0 KB)
    __shared__ float2 sU0[NQ][4];          // layer-0 full matrices (batch-dependent)
    __shared__ float  sT [DEPTH][NQ];      // shear coeff t = s'/c' (<=1), d>=1
    __shared__ float  sSc[DEPTH][NQ];      // per-gate scale c'
    __shared__ float2 sB1[DEPTH][NQ];      // B-diag b1 (b0 == 1 gauge), d>=1
    __shared__ float2 sA0[DEPTH][NQ];      // A-diag a0 (temp, for G0)
    __shared__ float2 sG [DEPTH][NQ];      // g = a1*conj(a0)
    __shared__ float2 sG0[DEPTH];          // prod_i a0[d][i], d=1..4
    __shared__ float  sCd[DEPTH];          // prod_i scale[d][i], d=1..5
    __shared__ int    sM [DEPTH];          // per-layer X-flip mask (wire i -> bit 11-i)
    __shared__ float2 sPhiA[DEPTH - 1][16];     // phase over t bits [7:4]
    __shared__ float2 sPhiB[DEPTH - 1][2][16];  // phase over t bits [3:0] (x bit4)
    __shared__ float2 sThi [DEPTH - 1][2][16];  // phase over r bits (x bit7 coupling)
    __shared__ float2 sW1[2][16];               // layer-1 fused product/diag table
    __shared__ float  sRed[NT / 32][NQ];

    const int t = threadIdx.x;
    const int b = blockIdx.x;

    if (t < DEPTH) sM[t] = 0;
    __syncthreads();

    // ================= Stage A: build gates; decompose U = (A*RY*B)*X =======
    if (t < DEPTH * NQ) {
        const int d = t / NQ, i = t % NQ;
        const float* pp = params + (d * NQ + i) * 3;
        float sa, ca, sb, cb, sg, cg;
        sincosf(0.5f * pp[0], &sa, &ca);
        sincosf(0.5f * pp[1], &sb, &cb);
        sincosf(0.5f * pp[2], &sg, &cg);
        float2 m00 = {  cb * ca, -sb * ca };
        float2 m01 = { -cb * sa,  sb * sa };
        float2 m10 = {  cb * sa,  sb * sa };
        float2 m11 = {  cb * ca,  sb * ca };
        float2 u00 = { cg * m00.x + sg * m10.y, cg * m00.y - sg * m10.x };
        float2 u01 = { cg * m01.x + sg * m11.y, cg * m01.y - sg * m11.x };
        float2 u10 = { sg * m00.y + cg * m10.x, -sg * m00.x + cg * m10.y };
        float2 u11 = { sg * m01.y + cg * m11.x, -sg * m01.x + cg * m11.y };
        if (d == 0) {
            float sx, cx;
            sincosf(0.5f * x[b * NQ + i], &sx, &cx);
            float2 v00 = { cx * u00.x + sx * u01.y,  cx * u00.y - sx * u01.x };
            float2 v01 = { sx * u00.y + cx * u01.x, -sx * u00.x + cx * u01.y };
            float2 v10 = { cx * u10.x + sx * u11.y,  cx * u10.y - sx * u11.x };
            float2 v11 = { sx * u10.y + cx * u11.x, -sx * u10.x + cx * u11.y };
            sU0[i][0] = v00; sU0[i][1] = v01; sU0[i][2] = v10; sU0[i][3] = v11;
        } else {
            float n00 = fmaf(u00.x, u00.x, u00.y * u00.y);
            float n10 = fmaf(u10.x, u10.x, u10.y * u10.y);
            bool swp = n10 > n00;     // V = U*X (column swap) so c' >= s'
            float2 v00, v10, v11;
            if (swp) { v00 = u01; v10 = u11; v11 = u10; atomicOr(&sM[d], 1 << (11 - i)); }
            else     { v00 = u00; v10 = u10; v11 = u11; }
            float c = sqrtf(fmaf(v00.x, v00.x, v00.y * v00.y));
            float s = sqrtf(fmaf(v10.x, v10.x, v10.y * v10.y));
            float ic = 1.0f / c;
            float2 a0 = { v00.x * ic, v00.y * ic };
            float2 a1, b1;
            if (s < 1e-12f) {
                a1 = { v11.x * ic, v11.y * ic };
                b1 = { 1.f, 0.f };
            } else {
                float is = 1.0f / s;
                a1 = { v10.x * is, v10.y * is };
                float2 tb = cmulc(v11, a1);
                b1 = { tb.x * ic, tb.y * ic };
            }
            sT [d][i] = s * ic;
            sSc[d][i] = c;
            sB1[d][i] = b1;
            sA0[d][i] = a0;
            sG [d][i] = cmulc(a1, a0);
        }
    }
    __syncthreads();

    // ================= Stage B: per-layer products =========================
    if (t >= 1 && t <= 5) {
        float cs = 1.f;
        #pragma unroll
        for (int i = 0; i < NQ; ++i) cs *= sSc[t][i];
        sCd[t] = cs;
        if (t <= 4) {
            float2 p = { 1.f, 0.f };
            #pragma unroll
            for (int i = 0; i < NQ; ++i) p = cmul(p, sA0[t][i]);
            sG0[t] = p;
        }
    }
    __syncthreads();

    // ================= Stage C: factorized diagonal tables =================
    // dst = (r<<8)|t ; src = gray(dst) ^ gm_d.
    // D_d(dst) = PhiA[t>>4] * PhiB[bit4(t)][t&15] * Thi[bit7(t)][r].
    if (t < (DEPTH - 1) * 16) {            // PhiA: t bits 7..4 (wires 4..7)
        const int k = t >> 4, h = t & 15;
        const int d = k + 1;
        const int mm = sM[d];
        const int gm = mm ^ (mm >> 1);
        float2 P = (d >= 2) ? sG0[d - 1] : make_float2(1.f, 0.f);
        const float cd = sCd[d];
        P.x *= cd; P.y *= cd;
        #pragma unroll
        for (int i = 4; i <= 7; ++i)       // wire i -> t bit (11-i) = h bit (7-i)
            if ((h >> (7 - i)) & 1) P = cmul(P, sB1[d][i]);
        if (d >= 2) {                      // couplings i=5,6,7: t bits (6,7),(5,6),(4,5)
            if (((h >> 2) ^ (h >> 3) ^ (gm >> 6)) & 1) P = cmul(P, sG[d - 1][5]);
            if (((h >> 1) ^ (h >> 2) ^ (gm >> 5)) & 1) P = cmul(P, sG[d - 1][6]);
            if (((h >> 0) ^ (h >> 1) ^ (gm >> 4)) & 1) P = cmul(P, sG[d - 1][7]);
        }
        sPhiA[k][h] = P;
    } else if (t < (DEPTH - 1) * 16 + (DEPTH - 1) * 32) {  // PhiB: t bits 3..0 (x bit4)
        const int tt = t - (DEPTH - 1) * 16;
        const int k = tt >> 5, e4 = (tt >> 4) & 1, l = tt & 15;
        const int d = k + 1;
        const int mm = sM[d];
        const int gm = mm ^ (mm >> 1);
        float2 P = { 1.f, 0.f };
        #pragma unroll
        for (int i = 8; i <= 11; ++i)      // wire i -> t bit (11-i) = l bit (11-i)
            if ((l >> (11 - i)) & 1) P = cmul(P, sB1[d][i]);
        if (d >= 2) {
            if (((l >> 3) ^ e4       ^ (gm >> 3)) & 1) P = cmul(P, sG[d - 1][8]);   // bits 3^4
            if (((l >> 2) ^ (l >> 3) ^ (gm >> 2)) & 1) P = cmul(P, sG[d - 1][9]);   // bits 2^3
            if (((l >> 1) ^ (l >> 2) ^ (gm >> 1)) & 1) P = cmul(P, sG[d - 1][10]);  // bits 1^2
            if (((l >> 0) ^ (l >> 1) ^ (gm >> 0)) & 1) P = cmul(P, sG[d - 1][11]);  // bits 0^1
        }
        sPhiB[k][e4][l] = P;
    }
    if (t < (DEPTH - 1) * 32) {            // Thi: wires 0..3 (+ couplings 0..4)
        const int k = t / 32, e = (t >> 4) & 1, r = t & 15;
        const int d = k + 1;
        const int mm = sM[d];
        const int gm = mm ^ (mm >> 1);
        float2 T = { 1.f, 0.f };
        #pragma unroll
        for (int i = 0; i < 4; ++i)
            if ((r >> (3 - i)) & 1) T = cmul(T, sB1[d][i]);
        if (d >= 2) {
            int r0 = r & 1, r1 = (r >> 1) & 1, r2 = (r >> 2) & 1, r3 = (r >> 3) & 1;
            if ((r3      ^ (gm >> 11)) & 1) T = cmul(T, sG[d - 1][0]);
            if ((r2 ^ r3 ^ (gm >> 10)) & 1) T = cmul(T, sG[d - 1][1]);
            if ((r1 ^ r2 ^ (gm >>  9)) & 1) T = cmul(T, sG[d - 1][2]);
            if ((r0 ^ r1 ^ (gm >>  8)) & 1) T = cmul(T, sG[d - 1][3]);
            if ((e  ^ r0 ^ (gm >>  7)) & 1) T = cmul(T, sG[d - 1][4]);
        }
        sThi[k][e][r] = T;
    }
    __syncthreads();

    // ================= Stage D: layer-1 fused table + per-thread phiF ======
    const int m1g = sM[1] ^ (sM[1] >> 1);
    if (t < 32) {
        const int e = t >> 4, r = t & 15;
        const int gr = (r ^ (r >> 1)) ^ ((m1g >> 8) & 15);
        float2 c01 = cmul(sU0[0][(gr & 8) ? 2 : 0], sU0[1][(gr & 4) ? 2 : 0]);
        float2 c23 = cmul(sU0[2][(gr & 2) ? 2 : 0], sU0[3][(gr & 1) ? 2 : 0]);
        float2 u4  = sU0[4][((e ^ r ^ (m1g >> 7)) & 1) ? 2 : 0];
        sW1[e][r] = cmul(cmul(c01, c23), cmul(u4, sThi[0][0][r]));
    }
    const int gt = t ^ (t >> 1);
    float2 phiF;
    {
        float2 p = cmul(sPhiA[0][t >> 4], sPhiB[0][(t >> 4) & 1][t & 15]);
        const int gmix = gt ^ m1g;
        #pragma unroll
        for (int i = 5; i < NQ; ++i) {
            int bit = (gmix >> (11 - i)) & 1;
            p = cmul(p, sU0[i][bit ? 2 : 0]);
        }
        phiF = p;
    }
    __syncthreads();

    // ===== addressing bases (pad-17: phys = idx + (idx>>4)) ================
    const int swt_p   = t + (t >> 4);                              // C store: + 272r
    const int baseB_p = (((t >> 4) << 8) | (t & 15)) + ((t >> 4) << 4);  // B: + 17v
    const int baseA_p = 17 * t;                                    // A: + r

    float2 s[PT];

    // ================= Layer 1 (peeled): no gather, tables only ============
    // NOTE on barriers:
    //  C->B boundary: round C writers span the whole CTA for any reader -> __syncthreads.
    //  B->A boundary: round A's reader t needs writers t' = (t & 0xF0) | r,
    //   the aligned 16-thread group containing t (always within one warp)
    //   -> __syncwarp() suffices (orders smem within the warp).
    //  A->C boundary: Gray gather varies bits 11..8 -> cross-warp -> __syncthreads.
    {
        const float2* w1 = sW1[t >> 7];
        #pragma unroll
        for (int r = 0; r < PT; ++r) s[r] = cmul(w1[r], phiF);
        gate4(s, sT[1][0], sT[1][1], sT[1][2], sT[1][3]);
        #pragma unroll
        for (int r = 0; r < PT; ++r) sS[swt_p + 272 * r] = s[r];
        __syncthreads();

        #pragma unroll
        for (int r = 0; r < PT; ++r) s[r] = sS[baseB_p + 17 * r];
        gate4(s, sT[1][4], sT[1][5], sT[1][6], sT[1][7]);
        #pragma unroll
        for (int r = 0; r < PT; ++r) sS[baseB_p + 17 * r] = s[r];
        __syncwarp();

        #pragma unroll
        for (int r = 0; r < PT; ++r) s[r] = sS[baseA_p + r];
        gate4(s, sT[1][8], sT[1][9], sT[1][10], sT[1][11]);
        #pragma unroll
        for (int r = 0; r < PT; ++r) sS[baseA_p + r] = s[r];
        __syncthreads();
    }

    // ================= Layers 2..5 (fully unrolled) ========================
    #pragma unroll
    for (int d = 2; d < DEPTH; ++d) {
        const int k = d - 1;

        // ---- Round C: Gray gather + diagonal fused into load, wires 0..3 --
        {
            const int mm = sM[d];
            const int gIdx = gt ^ (mm ^ (mm >> 1));
            const float2 phi = cmul(sPhiA[k][t >> 4], sPhiB[k][(t >> 4) & 1][t & 15]);
            const float2* thi = sThi[k][(t >> 7) & 1];
            #pragma unroll
            for (int r = 0; r < PT; ++r) {
                const int gr = r ^ (r >> 1);
                const int cr = (gr << 8) ^ ((r & 1) << 7);   // logical src bits
                const int idxl = gIdx ^ cr;
                s[r] = cmul(sS[idxl + (idxl >> 4)], cmul(phi, thi[r]));
            }
            __syncthreads();           // all reads of old state done
        }
        gate4(s, sT[d][0], sT[d][1], sT[d][2], sT[d][3]);
        #pragma unroll
        for (int r = 0; r < PT; ++r) sS[swt_p + 272 * r] = s[r];
        __syncthreads();

        // ---- Round B: wires 4..7 (per-thread disjoint addresses) ----
        #pragma unroll
        for (int r = 0; r < PT; ++r) s[r] = sS[baseB_p + 17 * r];
        gate4(s, sT[d][4], sT[d][5], sT[d][6], sT[d][7]);
        #pragma unroll
        for (int r = 0; r < PT; ++r) sS[baseB_p + 17 * r] = s[r];
        __syncwarp();                  // B->A exchange is within 16-thread groups

        // ---- Round A: wires 8..11 ----
        #pragma unroll
        for (int r = 0; r < PT; ++r) s[r] = sS[baseA_p + r];
        gate4(s, sT[d][8], sT[d][9], sT[d][10], sT[d][11]);
        if (d < DEPTH - 1) {
            #pragma unroll
            for (int r = 0; r < PT; ++r) sS[baseA_p + r] = s[r];
            __syncthreads();
        }
    }

    // ==== Final reduction directly from registers (idx = (t<<4)|r). ====
    float accLo[4] = { 0.f, 0.f, 0.f, 0.f };
    float sumAll = 0.f;
    #pragma unroll
    for (int r = 0; r < PT; ++r) {
        float pr = fmaf(s[r].x, s[r].x, s[r].y * s[r].y);
        sumAll += pr;
        const int r3 = (r >> 3) & 1, r2 = (r >> 2) & 1, r1 = (r >> 1) & 1, r0 = r & 1;
        const int p8 = r3, p9 = r3 ^ r2, p10 = p9 ^ r1, p11 = p10 ^ r0;
        accLo[0] += p8  ? -pr : pr;
        accLo[1] += p9  ? -pr : pr;
        accLo[2] += p10 ? -pr : pr;
        accLo[3] += p11 ? -pr : pr;
    }

    float acc[NQ];
    int pref = 0;
    #pragma unroll
    for (int q = 0; q < 8; ++q) {
        pref ^= (t >> (7 - q)) & 1;
        acc[q] = pref ? -sumAll : sumAll;
    }
    const int ptp = pref;
    #pragma unroll
    for (int q = 0; q < 4; ++q) acc[8 + q] = ptp ? -accLo[q] : accLo[q];

    #pragma unroll
    for (int q = 0; q < NQ; ++q) {
        #pragma unroll
        for (int off = 16; off; off >>= 1)
            acc[q] += __shfl_xor_sync(0xffffffffu, acc[q], off);
    }
    if ((t & 31) == 0) {
        #pragma unroll
        for (int q = 0; q < NQ; ++q) sRed[t >> 5][q] = acc[q];
    }
    __syncthreads();
    if (t < NQ) {
        float sres = 0.f;
        #pragma unroll
        for (int w = 0; w < NT / 32; ++w) sres += sRed[w][t];
        out[b * NQ + t] = sres;
    }
}

} // namespace

extern "C" void kernel_launch(void* const* d_in, const int* in_sizes, int n_in,
                              void* d_out, int out_size)
{
    (void)n_in; (void)out_size;
    const float* x;
    const float* params;
    if (in_sizes[0] == DEPTH * NQ * 3) {
        params = (const float*)d_in[0];
        x      = (const float*)d_in[1];
    } else {
        x      = (const float*)d_in[0];
        params = (const float*)d_in[1];
    }
    qsim_kernel<<<4096, NT>>>(x, params, (float*)d_out);
}

// round 16
// speedup vs baseline: 1.2120x; 1.1424x over previous
#include <cuda_runtime.h>

namespace {

constexpr int NQ     = 12;
constexpr int DEPTH  = 6;
constexpr int NSTATE = 1 << NQ;        // 4096
constexpr int NT     = 256;            // threads per CTA
constexpr int PT     = NSTATE / NT;    // 16 amplitudes per thread
constexpr int NPAD   = NSTATE + (NSTATE >> 4);   // 4352: pad-17 rows

typedef unsigned long long u64;

// Padded linear layout: phys(idx) = idx + (idx>>4) = 17*(idx>>4) + (idx&15).

__device__ __forceinline__ float2 cmul(float2 a, float2 b) {
    float2 r;
    r.x = fmaf(a.x, b.x, -(a.y * b.y));
    r.y = fmaf(a.x, b.y, a.y * b.x);
    return r;
}
__device__ __forceinline__ float2 cmulc(float2 a, float2 b) {  // a * conj(b)
    float2 r;
    r.x = fmaf(a.x, b.x,  a.y * b.y);
    r.y = fmaf(a.y, b.x, -(a.x * b.y));
    return r;
}

// ---- packed f32x2 helpers (both lanes of a 64-bit register pair) ----
__device__ __forceinline__ u64 pack2s(float v) {               // {v, v}
    u64 u; asm("mov.b64 %0, {%1,%1};" : "=l"(u) : "f"(v)); return u;
}
__device__ __forceinline__ u64 f2u(float2 v) {                 // {x, y}
    u64 u; asm("mov.b64 %0, {%1,%2};" : "=l"(u) : "f"(v.x), "f"(v.y)); return u;
}
__device__ __forceinline__ float2 u2f(u64 u) {
    float2 v; asm("mov.b64 {%0,%1}, %2;" : "=f"(v.x), "=f"(v.y) : "l"(u)); return v;
}
// packed shear pair: na = a - tv*b ; nb = tv*a + b   (2 FFMA2 instead of 4 FFMA)
__device__ __forceinline__ void sh2(u64& a, u64& b, u64 tv2, u64 ntv2) {
    u64 na, nb;
    asm("fma.rn.f32x2 %0, %1, %2, %3;" : "=l"(na) : "l"(ntv2), "l"(b), "l"(a));
    asm("fma.rn.f32x2 %0, %1, %2, %3;" : "=l"(nb) : "l"(tv2),  "l"(a), "l"(b));
    a = na; b = nb;
}
// 4 wires over local bits 3..0 (tv0 acts on bit 3, ..., tv3 on bit 0), packed
__device__ __forceinline__ void gate4p(u64* s, float t0, float t1, float t2, float t3) {
    const u64 p0 = pack2s(t0), n0 = pack2s(-t0);
    #pragma unroll
    for (int m = 0; m < 8; ++m) sh2(s[m], s[m + 8], p0, n0);
    const u64 p1 = pack2s(t1), n1 = pack2s(-t1);
    #pragma unroll
    for (int m = 0; m < 8; ++m) {
        int i0 = ((m >> 2) << 3) | (m & 3);
        sh2(s[i0], s[i0 | 4], p1, n1);
    }
    const u64 p2 = pack2s(t2), n2 = pack2s(-t2);
    #pragma unroll
    for (int m = 0; m < 8; ++m) {
        int i0 = ((m >> 1) << 2) | (m & 1);
        sh2(s[i0], s[i0 | 2], p2, n2);
    }
    const u64 p3 = pack2s(t3), n3 = pack2s(-t3);
    #pragma unroll
    for (int m = 0; m < 8; ++m) {
        int i0 = m << 1;
        sh2(s[i0], s[i0 | 1], p3, n3);
    }
}

__global__ void __launch_bounds__(NT, 4) qsim_kernel(const float* __restrict__ x,
                                                     const float* __restrict__ params,
                                                     float* __restrict__ out)
{
    __shared__ float2 sS[NPAD];            // state, padded layout (34.0 KB)
    __shared__ float2 sU0[NQ][4];          // layer-0 full matrices (batch-dependent)
    __shared__ float  sT [DEPTH][NQ];      // shear coeff t = s'/c' (<=1), d>=1
    __shared__ float  sSc[DEPTH][NQ];      // per-gate scale c'
    __shared__ float2 sB1[DEPTH][NQ];      // B-diag b1 (b0 == 1 gauge), d>=1
    __shared__ float2 sA0[DEPTH][NQ];      // A-diag a0 (temp, for G0)
    __shared__ float2 sG [DEPTH][NQ];      // g = a1*conj(a0)
    __shared__ float2 sG0[DEPTH];          // prod_i a0[d][i], d=1..4
    __shared__ float  sCd[DEPTH];          // prod_i scale[d][i], d=1..5
    __shared__ int    sM [DEPTH];          // per-layer X-flip mask (wire i -> bit 11-i)
    __shared__ float2 sPhiA[DEPTH - 1][16];     // phase over t bits [7:4]
    __shared__ float2 sPhiB[DEPTH - 1][2][16];  // phase over t bits [3:0] (x bit4)
    __shared__ float2 sThi [DEPTH - 1][2][16];  // phase over r bits (x bit7 coupling)
    __shared__ float2 sW1[2][16];               // layer-1 fused product/diag table
    __shared__ float  sRed[NT / 32][NQ];

    const int t = threadIdx.x;
    const int b = blockIdx.x;

    if (t < DEPTH) sM[t] = 0;
    __syncthreads();

    // ================= Stage A: build gates; decompose U = (A*RY*B)*X =======
    if (t < DEPTH * NQ) {
        const int d = t / NQ, i = t % NQ;
        const float* pp = params + (d * NQ + i) * 3;
        float sa, ca, sb, cb, sg, cg;
        sincosf(0.5f * pp[0], &sa, &ca);
        sincosf(0.5f * pp[1], &sb, &cb);
        sincosf(0.5f * pp[2], &sg, &cg);
        float2 m00 = {  cb * ca, -sb * ca };
        float2 m01 = { -cb * sa,  sb * sa };
        float2 m10 = {  cb * sa,  sb * sa };
        float2 m11 = {  cb * ca,  sb * ca };
        float2 u00 = { cg * m00.x + sg * m10.y, cg * m00.y - sg * m10.x };
        float2 u01 = { cg * m01.x + sg * m11.y, cg * m01.y - sg * m11.x };
        float2 u10 = { sg * m00.y + cg * m10.x, -sg * m00.x + cg * m10.y };
        float2 u11 = { sg * m01.y + cg * m11.x, -sg * m01.x + cg * m11.y };
        if (d == 0) {
            float sx, cx;
            sincosf(0.5f * x[b * NQ + i], &sx, &cx);
            float2 v00 = { cx * u00.x + sx * u01.y,  cx * u00.y - sx * u01.x };
            float2 v01 = { sx * u00.y + cx * u01.x, -sx * u00.x + cx * u01.y };
            float2 v10 = { cx * u10.x + sx * u11.y,  cx * u10.y - sx * u11.x };
            float2 v11 = { sx * u10.y + cx * u11.x, -sx * u10.x + cx * u11.y };
            sU0[i][0] = v00; sU0[i][1] = v01; sU0[i][2] = v10; sU0[i][3] = v11;
        } else {
            float n00 = fmaf(u00.x, u00.x, u00.y * u00.y);
            float n10 = fmaf(u10.x, u10.x, u10.y * u10.y);
            bool swp = n10 > n00;     // V = U*X (column swap) so c' >= s'
            float2 v00, v10, v11;
            if (swp) { v00 = u01; v10 = u11; v11 = u10; atomicOr(&sM[d], 1 << (11 - i)); }
            else     { v00 = u00; v10 = u10; v11 = u11; }
            float c = sqrtf(fmaf(v00.x, v00.x, v00.y * v00.y));
            float s = sqrtf(fmaf(v10.x, v10.x, v10.y * v10.y));
            float ic = 1.0f / c;
            float2 a0 = { v00.x * ic, v00.y * ic };
            float2 a1, b1;
            if (s < 1e-12f) {
                a1 = { v11.x * ic, v11.y * ic };
                b1 = { 1.f, 0.f };
            } else {
                float is = 1.0f / s;
                a1 = { v10.x * is, v10.y * is };
                float2 tb = cmulc(v11, a1);
                b1 = { tb.x * ic, tb.y * ic };
            }
            sT [d][i] = s * ic;
            sSc[d][i] = c;
            sB1[d][i] = b1;
            sA0[d][i] = a0;
            sG [d][i] = cmulc(a1, a0);
        }
    }
    __syncthreads();

    // ================= Stage B: per-layer products =========================
    if (t >= 1 && t <= 5) {
        float cs = 1.f;
        #pragma unroll
        for (int i = 0; i < NQ; ++i) cs *= sSc[t][i];
        sCd[t] = cs;
        if (t <= 4) {
            float2 p = { 1.f, 0.f };
            #pragma unroll
            for (int i = 0; i < NQ; ++i) p = cmul(p, sA0[t][i]);
            sG0[t] = p;
        }
    }
    __syncthreads();

    // ================= Stage C: factorized diagonal tables =================
    // dst = (r<<8)|t ; src = gray(dst) ^ gm_d.
    // D_d(dst) = PhiA[t>>4] * PhiB[bit4(t)][t&15] * Thi[bit7(t)][r].
    if (t < (DEPTH - 1) * 16) {            // PhiA: t bits 7..4 (wires 4..7)
        const int k = t >> 4, h = t & 15;
        const int d = k + 1;
        const int mm = sM[d];
        const int gm = mm ^ (mm >> 1);
        float2 P = (d >= 2) ? sG0[d - 1] : make_float2(1.f, 0.f);
        const float cd = sCd[d];
        P.x *= cd; P.y *= cd;
        #pragma unroll
        for (int i = 4; i <= 7; ++i)       // wire i -> t bit (11-i) = h bit (7-i)
            if ((h >> (7 - i)) & 1) P = cmul(P, sB1[d][i]);
        if (d >= 2) {                      // couplings i=5,6,7: t bits (6,7),(5,6),(4,5)
            if (((h >> 2) ^ (h >> 3) ^ (gm >> 6)) & 1) P = cmul(P, sG[d - 1][5]);
            if (((h >> 1) ^ (h >> 2) ^ (gm >> 5)) & 1) P = cmul(P, sG[d - 1][6]);
            if (((h >> 0) ^ (h >> 1) ^ (gm >> 4)) & 1) P = cmul(P, sG[d - 1][7]);
        }
        sPhiA[k][h] = P;
    } else if (t < (DEPTH - 1) * 16 + (DEPTH - 1) * 32) {  // PhiB: t bits 3..0 (x bit4)
        const int tt = t - (DEPTH - 1) * 16;
        const int k = tt >> 5, e4 = (tt >> 4) & 1, l = tt & 15;
        const int d = k + 1;
        const int mm = sM[d];
        const int gm = mm ^ (mm >> 1);
        float2 P = { 1.f, 0.f };
        #pragma unroll
        for (int i = 8; i <= 11; ++i)      // wire i -> t bit (11-i) = l bit (11-i)
            if ((l >> (11 - i)) & 1) P = cmul(P, sB1[d][i]);
        if (d >= 2) {
            if (((l >> 3) ^ e4       ^ (gm >> 3)) & 1) P = cmul(P, sG[d - 1][8]);   // bits 3^4
            if (((l >> 2) ^ (l >> 3) ^ (gm >> 2)) & 1) P = cmul(P, sG[d - 1][9]);   // bits 2^3
            if (((l >> 1) ^ (l >> 2) ^ (gm >> 1)) & 1) P = cmul(P, sG[d - 1][10]);  // bits 1^2
            if (((l >> 0) ^ (l >> 1) ^ (gm >> 0)) & 1) P = cmul(P, sG[d - 1][11]);  // bits 0^1
        }
        sPhiB[k][e4][l] = P;
    }
    if (t < (DEPTH - 1) * 32) {            // Thi: wires 0..3 (+ couplings 0..4)
        const int k = t / 32, e = (t >> 4) & 1, r = t & 15;
        const int d = k + 1;
        const int mm = sM[d];
        const int gm = mm ^ (mm >> 1);
        float2 T = { 1.f, 0.f };
        #pragma unroll
        for (int i = 0; i < 4; ++i)
            if ((r >> (3 - i)) & 1) T = cmul(T, sB1[d][i]);
        if (d >= 2) {
            int r0 = r & 1, r1 = (r >> 1) & 1, r2 = (r >> 2) & 1, r3 = (r >> 3) & 1;
            if ((r3      ^ (gm >> 11)) & 1) T = cmul(T, sG[d - 1][0]);
            if ((r2 ^ r3 ^ (gm >> 10)) & 1) T = cmul(T, sG[d - 1][1]);
            if ((r1 ^ r2 ^ (gm >>  9)) & 1) T = cmul(T, sG[d - 1][2]);
            if ((r0 ^ r1 ^ (gm >>  8)) & 1) T = cmul(T, sG[d - 1][3]);
            if ((e  ^ r0 ^ (gm >>  7)) & 1) T = cmul(T, sG[d - 1][4]);
        }
        sThi[k][e][r] = T;
    }
    __syncthreads();

    // ================= Stage D: layer-1 fused table + per-thread phiF ======
    const int m1g = sM[1] ^ (sM[1] >> 1);
    if (t < 32) {
        const int e = t >> 4, r = t & 15;
        const int gr = (r ^ (r >> 1)) ^ ((m1g >> 8) & 15);
        float2 c01 = cmul(sU0[0][(gr & 8) ? 2 : 0], sU0[1][(gr & 4) ? 2 : 0]);
        float2 c23 = cmul(sU0[2][(gr & 2) ? 2 : 0], sU0[3][(gr & 1) ? 2 : 0]);
        float2 u4  = sU0[4][((e ^ r ^ (m1g >> 7)) & 1) ? 2 : 0];
        sW1[e][r] = cmul(cmul(c01, c23), cmul(u4, sThi[0][0][r]));
    }
    const int gt = t ^ (t >> 1);
    float2 phiF;
    {
        float2 p = cmul(sPhiA[0][t >> 4], sPhiB[0][(t >> 4) & 1][t & 15]);
        const int gmix = gt ^ m1g;
        #pragma unroll
        for (int i = 5; i < NQ; ++i) {
            int bit = (gmix >> (11 - i)) & 1;
            p = cmul(p, sU0[i][bit ? 2 : 0]);
        }
        phiF = p;
    }
    __syncthreads();

    // ===== addressing bases (pad-17: phys = idx + (idx>>4)) ================
    const int swt_p   = t + (t >> 4);                              // C store: + 272r
    const int baseB_p = (((t >> 4) << 8) | (t & 15)) + ((t >> 4) << 4);  // B: + 17v
    const int baseA_p = 17 * t;                                    // A: + r

    u64 s[PT];                              // packed complex amplitudes

    // ================= Layer 1 (peeled): no gather, tables only ============
    {
        const float2* w1 = sW1[t >> 7];
        #pragma unroll
        for (int r = 0; r < PT; ++r) s[r] = f2u(cmul(w1[r], phiF));
        gate4p(s, sT[1][0], sT[1][1], sT[1][2], sT[1][3]);
        #pragma unroll
        for (int r = 0; r < PT; ++r)
            *reinterpret_cast<u64*>(&sS[swt_p + 272 * r]) = s[r];
        __syncthreads();

        #pragma unroll
        for (int r = 0; r < PT; ++r)
            s[r] = *reinterpret_cast<const u64*>(&sS[baseB_p + 17 * r]);
        gate4p(s, sT[1][4], sT[1][5], sT[1][6], sT[1][7]);
        #pragma unroll
        for (int r = 0; r < PT; ++r)
            *reinterpret_cast<u64*>(&sS[baseB_p + 17 * r]) = s[r];
        __syncwarp();

        #pragma unroll
        for (int r = 0; r < PT; ++r)
            s[r] = *reinterpret_cast<const u64*>(&sS[baseA_p + r]);
        gate4p(s, sT[1][8], sT[1][9], sT[1][10], sT[1][11]);
        #pragma unroll
        for (int r = 0; r < PT; ++r)
            *reinterpret_cast<u64*>(&sS[baseA_p + r]) = s[r];
        __syncthreads();
    }

    // ================= Layers 2..5 (fully unrolled) ========================
    #pragma unroll
    for (int d = 2; d < DEPTH; ++d) {
        const int k = d - 1;

        // ---- Round C: Gray gather + diagonal fused into load, wires 0..3 --
        {
            const int mm = sM[d];
            const int gIdx = gt ^ (mm ^ (mm >> 1));
            const float2 phi = cmul(sPhiA[k][t >> 4], sPhiB[k][(t >> 4) & 1][t & 15]);
            const float2* thi = sThi[k][(t >> 7) & 1];
            #pragma unroll
            for (int r = 0; r < PT; ++r) {
                const int gr = r ^ (r >> 1);
                const int cr = (gr << 8) ^ ((r & 1) << 7);   // logical src bits
                const int idxl = gIdx ^ cr;
                s[r] = f2u(cmul(sS[idxl + (idxl >> 4)], cmul(phi, thi[r])));
            }
            __syncthreads();           // all reads of old state done
        }
        gate4p(s, sT[d][0], sT[d][1], sT[d][2], sT[d][3]);
        #pragma unroll
        for (int r = 0; r < PT; ++r)
            *reinterpret_cast<u64*>(&sS[swt_p + 272 * r]) = s[r];
        __syncthreads();

        // ---- Round B: wires 4..7 (per-thread disjoint addresses) ----
        #pragma unroll
        for (int r = 0; r < PT; ++r)
            s[r] = *reinterpret_cast<const u64*>(&sS[baseB_p + 17 * r]);
        gate4p(s, sT[d][4], sT[d][5], sT[d][6], sT[d][7]);
        #pragma unroll
        for (int r = 0; r < PT; ++r)
            *reinterpret_cast<u64*>(&sS[baseB_p + 17 * r]) = s[r];
        __syncwarp();                  // B->A exchange is within 16-thread groups

        // ---- Round A: wires 8..11 ----
        #pragma unroll
        for (int r = 0; r < PT; ++r)
            s[r] = *reinterpret_cast<const u64*>(&sS[baseA_p + r]);
        gate4p(s, sT[d][8], sT[d][9], sT[d][10], sT[d][11]);
        if (d < DEPTH - 1) {
            #pragma unroll
            for (int r = 0; r < PT; ++r)
                *reinterpret_cast<u64*>(&sS[baseA_p + r]) = s[r];
            __syncthreads();
        }
    }

    // ==== Final reduction directly from registers (idx = (t<<4)|r). ====
    float accLo[4] = { 0.f, 0.f, 0.f, 0.f };
    float sumAll = 0.f;
    #pragma unroll
    for (int r = 0; r < PT; ++r) {
        float2 a = u2f(s[r]);
        float pr = fmaf(a.x, a.x, a.y * a.y);
        sumAll += pr;
        const int r3 = (r >> 3) & 1, r2 = (r >> 2) & 1, r1 = (r >> 1) & 1, r0 = r & 1;
        const int p8 = r3, p9 = r3 ^ r2, p10 = p9 ^ r1, p11 = p10 ^ r0;
        accLo[0] += p8  ? -pr : pr;
        accLo[1] += p9  ? -pr : pr;
        accLo[2] += p10 ? -pr : pr;
        accLo[3] += p11 ? -pr : pr;
    }

    float acc[NQ];
    int pref = 0;
    #pragma unroll
    for (int q = 0; q < 8; ++q) {
        pref ^= (t >> (7 - q)) & 1;
        acc[q] = pref ? -sumAll : sumAll;
    }
    const int ptp = pref;
    #pragma unroll
    for (int q = 0; q < 4; ++q) acc[8 + q] = ptp ? -accLo[q] : accLo[q];

    #pragma unroll
    for (int q = 0; q < NQ; ++q) {
        #pragma unroll
        for (int off = 16; off; off >>= 1)
            acc[q] += __shfl_xor_sync(0xffffffffu, acc[q], off);
    }
    if ((t & 31) == 0) {
        #pragma unroll
        for (int q = 0; q < NQ; ++q) sRed[t >> 5][q] = acc[q];
    }
    __syncthreads();
    if (t < NQ) {
        float sres = 0.f;
        #pragma unroll
        for (int w = 0; w < NT / 32; ++w) sres += sRed[w][t];
        out[b * NQ + t] = sres;
    }
}

} // namespace

extern "C" void kernel_launch(void* const* d_in, const int* in_sizes, int n_in,
                              void* d_out, int out_size)
{
    (void)n_in; (void)out_size;
    const float* x;
    const float* params;
    if (in_sizes[0] == DEPTH * NQ * 3) {
        params = (const float*)d_in[0];
        x      = (const float*)d_in[1];
    } else {
        x      = (const float*)d_in[0];
        params = (const float*)d_in[1];
    }
    qsim_kernel<<<4096, NT>>>(x, params, (float*)d_out);
}